// round 9
// baseline (speedup 1.0000x reference)
#include <cuda_runtime.h>
#include <cuda_bf16.h>
#include <cuda_pipeline_primitives.h>
#include <cstdint>

#define CC      2048
#define HW      49
#define SIDE    7
#define CGROUPS 8
#define NTHR    512
#define SPLIT   8
#define CPS     (CC / SPLIT)          // 256 channels per CTA
#define NMAX    256
#define NCHUNK  4
#define CHC     (CPS / NCHUNK)        // 64 channels per chunk
#define CHUNK_FLOATS (CHC * HW)       // 3136 floats = 12544 B
#define CHUNK_CPY16  (CHUNK_FLOATS / 4)  // 784 x 16B copies per chunk

// scratch: [n][split][p][5]
__device__ float g_scratch[NMAX * SPLIT * HW * 5];
__device__ int   g_count[NMAX];       // zero-init; last block resets its slot

__global__ __launch_bounds__(NTHR, 2)
void rpcp_fused_kernel(const float* __restrict__ x,
                       const float* __restrict__ Wlin,
                       const float* __restrict__ bias,
                       float* __restrict__ out,
                       float* __restrict__ scratch)
{
    __shared__ alignas(128) float buf[NCHUNK][CHUNK_FLOATS];   // 50176 B
    __shared__ float4 wsh[CPS];                                // 4 KB
    __shared__ float  acc[CGROUPS][HW][5];
    __shared__ int    s_last;
    __shared__ float  fin[HW][5];
    __shared__ float  gaps[HW];
    __shared__ float  dls[HW];
    __shared__ int    s_idx;
    __shared__ float  s_gmean;

    const int tid = threadIdx.x;
    const int n   = blockIdx.x >> 3;            // SPLIT = 8
    const int sp  = blockIdx.x & (SPLIT - 1);
    const int c0  = sp * CPS;

    // Issue ALL chunks up front, one commit group per chunk -> staged waits.
    {
        const float4* src = (const float4*)(x + (size_t)n * CC * HW + (size_t)c0 * HW);
        #pragma unroll
        for (int ch = 0; ch < NCHUNK; ch++) {
            float4* dst = (float4*)&buf[ch][0];
            const float4* s4 = src + ch * CHUNK_CPY16;
            for (int i = tid; i < CHUNK_CPY16; i += NTHR)
                __pipeline_memcpy_async(dst + i, s4 + i, 16);
            __pipeline_commit();
        }
    }

    // pack weight slice while copies fly: {W1_0, W1_1, W2_0, W2_1}
    for (int c = tid; c < CPS; c += NTHR) {
        const int cc = c0 + c;
        wsh[c] = make_float4(Wlin[cc],
                             Wlin[2 * CC + cc],
                             Wlin[CC + cc],
                             Wlin[3 * CC + cc]);
    }

    const int p  = tid & 63;     // 0..48 active
    const int cg = tid >> 6;     // 0..7 (warp-uniform)

    float s = 0.f, a0 = 0.f, a1 = 0.f, d0 = 0.f, d1 = 0.f;

    // staged consume: compute chunk ch while later chunks still stream
    #pragma unroll
    for (int ch = 0; ch < NCHUNK; ch++) {
        switch (ch) {   // wait until at most (NCHUNK-1-ch) groups still pending
            case 0: __pipeline_wait_prior(3); break;
            case 1: __pipeline_wait_prior(2); break;
            case 2: __pipeline_wait_prior(1); break;
            default: __pipeline_wait_prior(0); break;
        }
        __syncthreads();   // cross-thread visibility of this chunk
        if (p < HW) {
            #pragma unroll
            for (int u = 0; u < CHC / CGROUPS; u++) {   // 8 channels/thread/chunk
                const int cl = cg + u * CGROUPS;
                const float  v = buf[ch][cl * HW + p];  // smem
                const float4 w = wsh[ch * CHC + cl];    // warp-uniform broadcast
                s  += v;
                a0 = fmaf(v, w.x, a0);
                a1 = fmaf(v, w.y, a1);
                d0 = fmaf(v, w.z, d0);
                d1 = fmaf(v, w.w, d1);
            }
        }
    }

    if (p < HW) {
        acc[cg][p][0] = s;  acc[cg][p][1] = a0; acc[cg][p][2] = a1;
        acc[cg][p][3] = d0; acc[cg][p][4] = d1;
    }
    __syncthreads();

    if (tid < HW * 5) {
        const int pp = tid / 5, k = tid % 5;
        float t = 0.f;
        #pragma unroll
        for (int g = 0; g < CGROUPS; g++) t += acc[g][pp][k];
        scratch[((n * SPLIT + sp) * HW + pp) * 5 + k] = t;
    }

    // last-CTA-done handoff; fences by one thread only (cumulative via bar.sync)
    __syncthreads();
    if (tid == 0) {
        __threadfence();                       // release
        int old = atomicAdd(&g_count[n], 1);
        s_last = (old == SPLIT - 1);
        if (s_last) __threadfence();           // acquire
    }
    __syncthreads();
    if (!s_last) return;

    // ---- epilogue: this CTA finishes image n ----
    if (tid < HW * 5) {
        const int pp = tid / 5, k = tid % 5;
        float t = 0.f;
        #pragma unroll
        for (int g = 0; g < SPLIT; g++)
            t += scratch[((n * SPLIT + g) * HW + pp) * 5 + k];
        fin[pp][k] = t;
    }
    __syncthreads();

    // warp-shuffle argmax over channel-sum (first max wins ties)
    if (tid < 32) {
        float v  = fin[tid][0];
        int   bi = tid;
        if (tid + 32 < HW) {
            float v2 = fin[tid + 32][0];
            if (v2 > v) { v = v2; bi = tid + 32; }
        }
        #pragma unroll
        for (int off = 16; off > 0; off >>= 1) {
            float ov = __shfl_down_sync(0xffffffffu, v,  off);
            int   oi = __shfl_down_sync(0xffffffffu, bi, off);
            if (ov > v || (ov == v && oi < bi)) { v = ov; bi = oi; }
        }
        if (tid == 0) { s_idx = bi; g_count[n] = 0; }   // reset for replay
    }
    __syncthreads();
    const int idx = s_idx;

    if (tid < HW) {
        const float A0 = fin[idx][1];
        const float A1 = fin[idx][2];
        float pr0 = fin[tid][3] + A0 + bias[0];
        float pr1 = fin[tid][4] + A1 + bias[1];
        pr0 = fmaxf(pr0, 0.f);
        pr1 = fmaxf(pr1, 0.f);
        if (tid == idx) { pr0 = 0.f; pr1 = 0.f; }

        const float ri = (float)(tid / SIDE - idx / SIDE) * (1.f / (float)SIDE);
        const float rj = (float)(tid % SIDE - idx % SIDE) * (1.f / (float)SIDE);
        const float rd = sqrtf(ri * ri + rj * rj);
        const float ang = (atan2f(rj, ri) * (1.f / 3.14159265358979323846f) + 1.f) * 0.5f;

        float dl = pr0 - rd; dl *= dl;
        float g  = pr1 - ang;
        if (g < 0.f) g += 1.f;
        gaps[tid] = g;
        dls[tid]  = dl;
    }
    __syncthreads();

    // warp-shuffle mean of gaps
    if (tid < 32) {
        float t = (tid < HW) ? gaps[tid] : 0.f;
        if (tid + 32 < HW) t += gaps[tid + 32];
        #pragma unroll
        for (int off = 16; off > 0; off >>= 1)
            t += __shfl_down_sync(0xffffffffu, t, off);
        if (tid == 0) s_gmean = t * (1.f / (float)HW);
    }
    __syncthreads();

    if (tid < HW) {
        float g = gaps[tid] - s_gmean;
        out[n * HW + tid] = dls[tid] + g * g;
    }
}

extern "C" void kernel_launch(void* const* d_in, const int* in_sizes, int n_in,
                              void* d_out, int out_size)
{
    const float* x    = (const float*)d_in[0];
    const float* Wlin = (const float*)d_in[1];
    const float* b    = (const float*)d_in[2];
    float*       out  = (float*)d_out;

    const int N = in_sizes[0] / (CC * HW);   // 256

    float* scratch = nullptr;
    cudaGetSymbolAddress((void**)&scratch, g_scratch);

    rpcp_fused_kernel<<<N * SPLIT, NTHR>>>(x, Wlin, b, out, scratch);
}